// round 14
// baseline (speedup 1.0000x reference)
#include <cuda_runtime.h>
#include <cstdint>

#define HH 256
#define WW 256
#define NC 80
#define HWSZ 65536
#define KTOP 100
#define MAXCAND 8192
#define NBKT 8192
#define CAP  1024
#define BAND 32

// scratch (no cudaMalloc allowed); zero-init at load, reset at end of pipeline
__device__ unsigned int        g_count[NC];
__device__ unsigned long long  g_cand[NC][MAXCAND];   // (fkey<<32)|(65535-idx)
__device__ unsigned int        g_hist[NBKT];
__device__ unsigned int        g_selcnt;
__device__ unsigned int        g_done;
__device__ unsigned long long  g_sel[CAP];

// monotone float->uint key (handles negatives)
__device__ __forceinline__ unsigned int fkey(float f) {
    unsigned int b = __float_as_uint(f);
    return b ^ ((b & 0x80000000u) ? 0xFFFFFFFFu : 0x80000000u);
}
__device__ __forceinline__ float fkeyinv(unsigned int k) {
    unsigned int b = k ^ ((k & 0x80000000u) ? 0x80000000u : 0xFFFFFFFFu);
    return __uint_as_float(b);
}
__device__ __forceinline__ float4 f4max(float4 a, float4 b) {
    return make_float4(fmaxf(a.x, b.x), fmaxf(a.y, b.y),
                       fmaxf(a.z, b.z), fmaxf(a.w, b.w));
}
// 64-bit global order key: (score desc, class asc, idx asc) == descending numeric
__device__ __forceinline__ unsigned long long gkey(unsigned long long ck, int c) {
    return ((ck >> 32) << 23)
         | ((unsigned long long)(79 - c) << 16)
         | (ck & 0xFFFFull);
}

// 5x5 strict-window max on logits of batch 0 (R10 fast version)
// + fire-and-forget histogram REDs (spread addresses, no return dependence).
__global__ __launch_bounds__(256, 4) void suppress_kernel(const float* __restrict__ cls) {
    __shared__ float smvm[BAND][WW + 8];
    const int c   = blockIdx.y;
    const int y0  = blockIdx.x * BAND;
    const int tid = threadIdx.x;
    const int tx  = tid & 63;
    const int ty  = tid >> 6;
    const int lane = tid & 31;
    const float NEG = __int_as_float(0xff800000);
    const float4 NEG4 = make_float4(NEG, NEG, NEG, NEG);
    const float* __restrict__ p = cls + ((size_t)c << 16);
    const float4* __restrict__ p4 = reinterpret_cast<const float4*>(p);

    {
        float4 v[12];
        const int ybase = y0 + ty * 8 - 2;
        #pragma unroll
        for (int r = 0; r < 12; r++) {
            int gy = ybase + r;
            v[r] = (gy >= 0 && gy < HH) ? p4[(gy << 6) | tx] : NEG4;
        }
        {
            int r = tid >> 3, s = tid & 7;
            smvm[r][(s < 4) ? s : (WW + s)] = NEG;
        }
        #pragma unroll
        for (int r = 0; r < 8; r++) {
            float4 vm = f4max(f4max(f4max(v[r], v[r + 1]),
                                    f4max(v[r + 2], v[r + 3])), v[r + 4]);
            *reinterpret_cast<float4*>(&smvm[ty * 8 + r][4 + tx * 4]) = vm;
        }
    }
    __syncthreads();

    unsigned int bm = 0;
    #pragma unroll 2
    for (int r = 0; r < 8; r++) {
        const float* row = smvm[ty * 8 + r];
        float4 L = *reinterpret_cast<const float4*>(&row[tx * 4]);
        float4 C = *reinterpret_cast<const float4*>(&row[tx * 4 + 4]);
        float4 R = *reinterpret_cast<const float4*>(&row[tx * 4 + 8]);
        int rowg = y0 + ty * 8 + r;
        float4 cen = p4[(rowg << 6) | tx];          // L1 hit

        float m12 = fmaxf(C.y, C.z);
        float aa  = fmaxf(C.x, m12);
        float bb  = fmaxf(m12, C.w);
        float ab  = fmaxf(aa, C.w);
        float h0  = fmaxf(fmaxf(L.z, L.w), aa);
        float h1  = fmaxf(L.w, ab);
        float h2  = fmaxf(ab, R.x);
        float h3  = fmaxf(bb, fmaxf(R.x, R.y));

        bm |= (unsigned int)(cen.x == h0) << (r * 4 + 0);
        bm |= (unsigned int)(cen.y == h1) << (r * 4 + 1);
        bm |= (unsigned int)(cen.z == h2) << (r * 4 + 2);
        bm |= (unsigned int)(cen.w == h3) << (r * 4 + 3);
    }

    unsigned int nloc = (unsigned int)__popc(bm);
    unsigned int inc = nloc;
    #pragma unroll
    for (int o = 1; o < 32; o <<= 1) {
        unsigned int t = __shfl_up_sync(0xFFFFFFFFu, inc, o);
        if (lane >= o) inc += t;
    }
    unsigned int total = __shfl_sync(0xFFFFFFFFu, inc, 31);
    if (total) {
        unsigned int base = 0;
        if (lane == 31) base = atomicAdd(&g_count[c], total);   // per-class shard
        base = __shfl_sync(0xFFFFFFFFu, base, 31);
        unsigned int pos = base + inc - nloc;
        while (bm) {
            int b = __ffs(bm) - 1;
            bm &= bm - 1;
            int r = b >> 2, s = b & 3;
            int idx = ((y0 + ty * 8 + r) << 8) | (tx * 4 + s);
            float val = p[idx];                     // L1 hit
            unsigned int fk = fkey(val);
            atomicAdd(&g_hist[fk >> 19], 1u);       // RED (no return use), spread
            if (pos < MAXCAND)
                g_cand[c][pos] = ((unsigned long long)fk << 32)
                               | (unsigned int)(65535 - idx);
            pos++;
        }
    }
}

// Find smallest bucket B with suffix_count(>=B) >= need over hist[NBKT].
// Block-collective, 1024 threads; warp-parallel. out3: {B, above, suffix(B)}.
__device__ void find_boundary(const unsigned int* hist, unsigned int* psums,
                              unsigned int* wsums, unsigned int need,
                              unsigned int* out3) {
    const int tid = threadIdx.x;
    unsigned int pv0 = 0;
    const int base = tid * 8;
    #pragma unroll
    for (int k = 0; k < 8; k++) pv0 += hist[base + k];
    unsigned int w = pv0;
    #pragma unroll
    for (int o = 16; o; o >>= 1) w += __shfl_down_sync(0xFFFFFFFFu, w, o);
    psums[tid] = pv0;
    if ((tid & 31) == 0) wsums[tid >> 5] = w;
    __syncthreads();
    if (tid < 32) {
        unsigned int wv = wsums[tid];
        unsigned int suf = wv;
        #pragma unroll
        for (int o = 1; o < 32; o <<= 1) {
            unsigned int t = __shfl_down_sync(0xFFFFFFFFu, suf, o);
            if (tid + o < 32) suf += t;
        }
        unsigned int m = __ballot_sync(0xFFFFFFFFu, suf >= need);
        int wstar = m ? (31 - __clz(m)) : 0;
        unsigned int acc = __shfl_sync(0xFFFFFFFFu, suf - wv, wstar);
        unsigned int pv = psums[wstar * 32 + tid];
        unsigned int sufp = pv;
        #pragma unroll
        for (int o = 1; o < 32; o <<= 1) {
            unsigned int t = __shfl_down_sync(0xFFFFFFFFu, sufp, o);
            if (tid + o < 32) sufp += t;
        }
        m = __ballot_sync(0xFFFFFFFFu, acc + sufp >= need);
        int tstar = m ? (31 - __clz(m)) : 0;
        acc = __shfl_sync(0xFFFFFFFFu, acc + sufp - pv, tstar);
        int tglob = wstar * 32 + tstar;
        unsigned int hv = (tid < 8) ? hist[tglob * 8 + tid] : 0;
        unsigned int sufh = hv;
        #pragma unroll
        for (int o = 1; o < 8; o <<= 1) {
            unsigned int t = __shfl_down_sync(0xFFFFFFFFu, sufh, o);
            if (tid + o < 32) sufh += t;
        }
        m = __ballot_sync(0xFFFFFFFFu, (tid < 8) && (acc + sufh >= need)) & 0xFFu;
        int bstar = m ? (31 - __clz(m)) : 0;
        acc = __shfl_sync(0xFFFFFFFFu, acc + sufh - hv, bstar);
        if (tid == 0) {
            unsigned int B = (unsigned int)(tglob * 8 + bstar);
            out3[0] = B;
            out3[1] = acc;
            out3[2] = acc + hist[B];
        }
    }
    __syncthreads();
}

// One fused kernel: boundary -> per-class compaction -> ticket -> last block:
// rank-select top-100 (no sort), decode, write, reset scratch.
__global__ __launch_bounds__(1024) void select_kernel(
        const float* __restrict__ txty,
        const float* __restrict__ twth,
        float* __restrict__ out) {
    __shared__ unsigned int psums[1024];
    __shared__ unsigned int wsums[32];
    __shared__ unsigned int bout[3];
    __shared__ unsigned int shist[NBKT];
    __shared__ unsigned long long sel[CAP];
    __shared__ unsigned int s_n;
    __shared__ unsigned int s_last;

    const int c = blockIdx.x;
    const int tid = threadIdx.x;
    const int lane = tid & 31;

    find_boundary(g_hist, psums, wsums, KTOP, bout);
    unsigned int B1 = bout[0], above = bout[1], sfx = bout[2];

    // ---- per-class compaction (fast path only) ----
    if (sfx <= CAP) {
        unsigned int n = min(g_count[c], (unsigned int)MAXCAND);
        for (unsigned int i = tid; i < ((n + 1023u) & ~1023u); i += 1024) {
            unsigned long long ck = (i < n) ? g_cand[c][i] : 0ULL;
            bool take = (i < n) && ((unsigned int)(ck >> 51) >= B1);
            unsigned int mask = __ballot_sync(0xFFFFFFFFu, take);
            if (mask) {
                int leader = __ffs(mask) - 1;
                unsigned int basep = 0;
                if (lane == leader) basep = atomicAdd(&g_selcnt, (unsigned int)__popc(mask));
                basep = __shfl_sync(0xFFFFFFFFu, basep, leader);
                if (take) {
                    unsigned int posw = basep + __popc(mask & ((1u << lane) - 1));
                    if (posw < CAP) g_sel[posw] = gkey(ck, c);
                }
            }
        }
    }

    // ---- ticket: last block proceeds ----
    __syncthreads();
    __threadfence();
    if (tid == 0) s_last = atomicAdd(&g_done, 1u);
    __syncthreads();
    if (s_last != NC - 1) return;

    // ---- final phase (one block) ----
    if (sfx <= CAP) {
        unsigned int n = min(g_selcnt, (unsigned int)CAP);
        for (unsigned int i = tid; i < n; i += 1024) sel[i] = g_sel[i];
        if (tid == 0) s_n = n;
    } else {
        // exact slow path: radix refinement over per-class arrays (massive-tie case)
        unsigned long long prefix = B1;
        unsigned int need = KTOP - above;
        int s = 42;
        for (int lvl = 0; lvl < 3; lvl++) {
            s -= 13;
            for (int i = tid; i < NBKT; i += 1024) shist[i] = 0;
            __syncthreads();
            for (int cc = 0; cc < NC; cc++) {
                unsigned int n = min(g_count[cc], (unsigned int)MAXCAND);
                for (unsigned int i = tid; i < n; i += 1024) {
                    unsigned long long k = gkey(g_cand[cc][i], cc);
                    if ((k >> (s + 13)) == prefix)
                        atomicAdd(&shist[(unsigned int)(k >> s) & 8191u], 1u);
                }
            }
            __syncthreads();
            find_boundary(shist, psums, wsums, need, bout);
            prefix = (prefix << 13) | bout[0];
            need -= bout[1];
            if (bout[2] <= CAP - KTOP || s == 3) break;
            __syncthreads();
        }
        if (tid == 0) s_n = 0;
        __syncthreads();
        for (int cc = 0; cc < NC; cc++) {
            unsigned int n = min(g_count[cc], (unsigned int)MAXCAND);
            for (unsigned int i = tid; i < n; i += 1024) {
                unsigned long long k = gkey(g_cand[cc][i], cc);
                if ((k >> s) >= prefix) {
                    unsigned int pos = atomicAdd(&s_n, 1u);
                    if (pos < CAP) sel[pos] = k;
                }
            }
        }
    }
    __syncthreads();

    // ---- rank-select (keys unique => exact): rank = #{keys > mine} ----
    unsigned int n = min(s_n, (unsigned int)CAP);
    if (tid < (int)n) {
        unsigned long long my = sel[tid];
        unsigned int rank = 0;
        for (unsigned int j = 0; j < n; j++)
            rank += (sel[j] > my);
        if (rank < KTOP) {
            unsigned int fk = (unsigned int)(my >> 23);
            int cls = 79 - (int)((my >> 16) & 127ull);
            int spatial = 65535 - (int)(my & 0xFFFFull);
            float logit = fkeyinv(fk);
            float score = 1.0f / (1.0f + expf(-logit));

            int y = spatial >> 8, x = spatial & 255;
            float tx = txty[spatial];
            float ty = txty[HWSZ + spatial];
            float tw = twth[spatial];
            float th = twth[HWSZ + spatial];

            float cx = ((float)x + 1.0f / (1.0f + expf(-tx))) * 4.0f;
            float cy = ((float)y + 1.0f / (1.0f + expf(-ty))) * 4.0f;
            float w2 = expf(tw) * 2.0f;
            float h2 = expf(th) * 2.0f;
            const float inv = 1.0f / 1024.0f;

            out[rank * 4 + 0] = fminf(fmaxf((cx - w2) * inv, 0.0f), 1.0f);
            out[rank * 4 + 1] = fminf(fmaxf((cy - h2) * inv, 0.0f), 1.0f);
            out[rank * 4 + 2] = fminf(fmaxf((cx + w2) * inv, 0.0f), 1.0f);
            out[rank * 4 + 3] = fminf(fmaxf((cy + h2) * inv, 0.0f), 1.0f);
            out[4 * KTOP + rank] = score;
            out[5 * KTOP + rank] = (float)cls;
        }
    }

    // ---- reset scratch for next launch (determinism across graph replays) ----
    __syncthreads();
    for (int i = tid; i < NBKT; i += 1024) g_hist[i] = 0;
    if (tid < NC) g_count[tid] = 0;
    if (tid == 0) { g_selcnt = 0; g_done = 0; }
}

extern "C" void kernel_launch(void* const* d_in, const int* in_sizes, int n_in,
                              void* d_out, int out_size) {
    const float* cls  = (const float*)d_in[0];
    const float* txty = (const float*)d_in[1];
    const float* twth = (const float*)d_in[2];
    float* out = (float*)d_out;

    dim3 grid(HH / BAND, NC);
    suppress_kernel<<<grid, 256>>>(cls);
    select_kernel<<<NC, 1024>>>(txty, twth, out);
}

// round 15
// speedup vs baseline: 1.0007x; 1.0007x over previous
#include <cuda_runtime.h>
#include <cstdint>

#define HH 256
#define WW 256
#define NC 80
#define HWSZ 65536
#define KTOP 100
#define MAXCAND 8192
#define NBKT 8192
#define CAP  1024
#define BAND 32

// scratch (no cudaMalloc allowed); zero-init at load, reset at end of pipeline
__device__ unsigned int        g_count[NC];
__device__ unsigned long long  g_cand[NC][MAXCAND];   // (fkey<<32)|(65535-idx)
__device__ unsigned int        g_hist[NBKT];
__device__ unsigned int        g_selcnt;
__device__ unsigned int        g_done1;
__device__ unsigned int        g_done2;
__device__ unsigned int        g_phase;
__device__ unsigned long long  g_sel[CAP];

// monotone float->uint key (handles negatives)
__device__ __forceinline__ unsigned int fkey(float f) {
    unsigned int b = __float_as_uint(f);
    return b ^ ((b & 0x80000000u) ? 0xFFFFFFFFu : 0x80000000u);
}
__device__ __forceinline__ float fkeyinv(unsigned int k) {
    unsigned int b = k ^ ((k & 0x80000000u) ? 0x80000000u : 0xFFFFFFFFu);
    return __uint_as_float(b);
}
__device__ __forceinline__ float4 f4max(float4 a, float4 b) {
    return make_float4(fmaxf(a.x, b.x), fmaxf(a.y, b.y),
                       fmaxf(a.z, b.z), fmaxf(a.w, b.w));
}
// 64-bit global order key: (score desc, class asc, idx asc) == descending numeric
__device__ __forceinline__ unsigned long long gkey(unsigned long long ck, int c) {
    return ((ck >> 32) << 23)
         | ((unsigned long long)(79 - c) << 16)
         | (ck & 0xFFFFull);
}

// 5x5 strict-window max on logits of batch 0 (exact R10 fast version, no hist).
__global__ __launch_bounds__(256, 4) void suppress_kernel(const float* __restrict__ cls) {
    __shared__ float smvm[BAND][WW + 8];
    const int c   = blockIdx.y;
    const int y0  = blockIdx.x * BAND;
    const int tid = threadIdx.x;
    const int tx  = tid & 63;
    const int ty  = tid >> 6;
    const int lane = tid & 31;
    const float NEG = __int_as_float(0xff800000);
    const float4 NEG4 = make_float4(NEG, NEG, NEG, NEG);
    const float* __restrict__ p = cls + ((size_t)c << 16);
    const float4* __restrict__ p4 = reinterpret_cast<const float4*>(p);

    {
        float4 v[12];
        const int ybase = y0 + ty * 8 - 2;
        #pragma unroll
        for (int r = 0; r < 12; r++) {
            int gy = ybase + r;
            v[r] = (gy >= 0 && gy < HH) ? p4[(gy << 6) | tx] : NEG4;
        }
        {
            int r = tid >> 3, s = tid & 7;
            smvm[r][(s < 4) ? s : (WW + s)] = NEG;
        }
        #pragma unroll
        for (int r = 0; r < 8; r++) {
            float4 vm = f4max(f4max(f4max(v[r], v[r + 1]),
                                    f4max(v[r + 2], v[r + 3])), v[r + 4]);
            *reinterpret_cast<float4*>(&smvm[ty * 8 + r][4 + tx * 4]) = vm;
        }
    }
    __syncthreads();

    unsigned int bm = 0;
    #pragma unroll 2
    for (int r = 0; r < 8; r++) {
        const float* row = smvm[ty * 8 + r];
        float4 L = *reinterpret_cast<const float4*>(&row[tx * 4]);
        float4 C = *reinterpret_cast<const float4*>(&row[tx * 4 + 4]);
        float4 R = *reinterpret_cast<const float4*>(&row[tx * 4 + 8]);
        int rowg = y0 + ty * 8 + r;
        float4 cen = p4[(rowg << 6) | tx];          // L1 hit

        float m12 = fmaxf(C.y, C.z);
        float aa  = fmaxf(C.x, m12);
        float bb  = fmaxf(m12, C.w);
        float ab  = fmaxf(aa, C.w);
        float h0  = fmaxf(fmaxf(L.z, L.w), aa);
        float h1  = fmaxf(L.w, ab);
        float h2  = fmaxf(ab, R.x);
        float h3  = fmaxf(bb, fmaxf(R.x, R.y));

        bm |= (unsigned int)(cen.x == h0) << (r * 4 + 0);
        bm |= (unsigned int)(cen.y == h1) << (r * 4 + 1);
        bm |= (unsigned int)(cen.z == h2) << (r * 4 + 2);
        bm |= (unsigned int)(cen.w == h3) << (r * 4 + 3);
    }

    unsigned int nloc = (unsigned int)__popc(bm);
    unsigned int inc = nloc;
    #pragma unroll
    for (int o = 1; o < 32; o <<= 1) {
        unsigned int t = __shfl_up_sync(0xFFFFFFFFu, inc, o);
        if (lane >= o) inc += t;
    }
    unsigned int total = __shfl_sync(0xFFFFFFFFu, inc, 31);
    if (total) {
        unsigned int base = 0;
        if (lane == 31) base = atomicAdd(&g_count[c], total);
        base = __shfl_sync(0xFFFFFFFFu, base, 31);
        unsigned int pos = base + inc - nloc;
        while (bm) {
            int b = __ffs(bm) - 1;
            bm &= bm - 1;
            int r = b >> 2, s = b & 3;
            int idx = ((y0 + ty * 8 + r) << 8) | (tx * 4 + s);
            float val = p[idx];                     // L1 hit
            if (pos < MAXCAND)
                g_cand[c][pos] = ((unsigned long long)fkey(val) << 32)
                               | (unsigned int)(65535 - idx);
            pos++;
        }
    }
}

// Find smallest bucket B with suffix_count(>=B) >= need over hist[NBKT].
// Block-collective, 1024 threads; warp-parallel. out3: {B, above, suffix(B)}.
__device__ void find_boundary(const unsigned int* hist, unsigned int* psums,
                              unsigned int* wsums, unsigned int need,
                              unsigned int* out3) {
    const int tid = threadIdx.x;
    unsigned int pv0 = 0;
    const int base = tid * 8;
    #pragma unroll
    for (int k = 0; k < 8; k++) pv0 += hist[base + k];
    unsigned int w = pv0;
    #pragma unroll
    for (int o = 16; o; o >>= 1) w += __shfl_down_sync(0xFFFFFFFFu, w, o);
    psums[tid] = pv0;
    if ((tid & 31) == 0) wsums[tid >> 5] = w;
    __syncthreads();
    if (tid < 32) {
        unsigned int wv = wsums[tid];
        unsigned int suf = wv;
        #pragma unroll
        for (int o = 1; o < 32; o <<= 1) {
            unsigned int t = __shfl_down_sync(0xFFFFFFFFu, suf, o);
            if (tid + o < 32) suf += t;
        }
        unsigned int m = __ballot_sync(0xFFFFFFFFu, suf >= need);
        int wstar = m ? (31 - __clz(m)) : 0;
        unsigned int acc = __shfl_sync(0xFFFFFFFFu, suf - wv, wstar);
        unsigned int pv = psums[wstar * 32 + tid];
        unsigned int sufp = pv;
        #pragma unroll
        for (int o = 1; o < 32; o <<= 1) {
            unsigned int t = __shfl_down_sync(0xFFFFFFFFu, sufp, o);
            if (tid + o < 32) sufp += t;
        }
        m = __ballot_sync(0xFFFFFFFFu, acc + sufp >= need);
        int tstar = m ? (31 - __clz(m)) : 0;
        acc = __shfl_sync(0xFFFFFFFFu, acc + sufp - pv, tstar);
        int tglob = wstar * 32 + tstar;
        unsigned int hv = (tid < 8) ? hist[tglob * 8 + tid] : 0;
        unsigned int sufh = hv;
        #pragma unroll
        for (int o = 1; o < 8; o <<= 1) {
            unsigned int t = __shfl_down_sync(0xFFFFFFFFu, sufh, o);
            if (tid + o < 32) sufh += t;
        }
        m = __ballot_sync(0xFFFFFFFFu, (tid < 8) && (acc + sufh >= need)) & 0xFFu;
        int bstar = m ? (31 - __clz(m)) : 0;
        acc = __shfl_sync(0xFFFFFFFFu, acc + sufh - hv, bstar);
        if (tid == 0) {
            unsigned int B = (unsigned int)(tglob * 8 + bstar);
            out3[0] = B;
            out3[1] = acc;
            out3[2] = acc + hist[B];
        }
    }
    __syncthreads();
}

// One kernel, 80 co-resident blocks (grid < #SMs => spin-safe):
// phase1 hist REDs -> grid barrier -> boundary -> compaction -> ticket ->
// last block: rank-select (no sort), decode, write, reset.
__global__ __launch_bounds__(1024) void select_kernel(
        const float* __restrict__ txty,
        const float* __restrict__ twth,
        float* __restrict__ out) {
    __shared__ unsigned int psums[1024];
    __shared__ unsigned int wsums[32];
    __shared__ unsigned int bout[3];
    __shared__ unsigned int shist[NBKT];
    __shared__ unsigned long long sel[CAP];
    __shared__ unsigned int s_n;
    __shared__ unsigned int s_last;

    const int c = blockIdx.x;
    const int tid = threadIdx.x;
    const int lane = tid & 31;
    const unsigned int n_c = min(g_count[c], (unsigned int)MAXCAND);

    // ---- phase 1: histogram this class's candidates (spread REDs) ----
    for (unsigned int i = tid; i < n_c; i += 1024) {
        unsigned int fk = (unsigned int)(g_cand[c][i] >> 32);
        atomicAdd(&g_hist[fk >> 19], 1u);
    }

    // ---- grid barrier (all 80 blocks co-resident) ----
    __syncthreads();
    __threadfence();
    if (tid == 0) {
        unsigned int arrived = atomicAdd(&g_done1, 1u) + 1u;
        if (arrived == NC) atomicExch(&g_phase, 1u);
        else while (atomicCAS(&g_phase, 1u, 1u) == 0u) __nanosleep(64);
    }
    __syncthreads();
    __threadfence();

    // ---- boundary (hist now L2-hot) ----
    find_boundary(g_hist, psums, wsums, KTOP, bout);
    unsigned int B1 = bout[0], above = bout[1], sfx = bout[2];

    // ---- per-class compaction (fast path only) ----
    if (sfx <= CAP) {
        for (unsigned int i = tid; i < ((n_c + 1023u) & ~1023u); i += 1024) {
            unsigned long long ck = (i < n_c) ? g_cand[c][i] : 0ULL;
            bool take = (i < n_c) && ((unsigned int)(ck >> 51) >= B1);
            unsigned int mask = __ballot_sync(0xFFFFFFFFu, take);
            if (mask) {
                int leader = __ffs(mask) - 1;
                unsigned int basep = 0;
                if (lane == leader) basep = atomicAdd(&g_selcnt, (unsigned int)__popc(mask));
                basep = __shfl_sync(0xFFFFFFFFu, basep, leader);
                if (take) {
                    unsigned int posw = basep + __popc(mask & ((1u << lane) - 1));
                    if (posw < CAP) g_sel[posw] = gkey(ck, c);
                }
            }
        }
    }

    // ---- ticket: last block proceeds to final phase ----
    __syncthreads();
    __threadfence();
    if (tid == 0) s_last = atomicAdd(&g_done2, 1u);
    __syncthreads();
    if (s_last != NC - 1) return;

    // ---- final phase (one block) ----
    if (sfx <= CAP) {
        unsigned int n = min(g_selcnt, (unsigned int)CAP);
        for (unsigned int i = tid; i < n; i += 1024) sel[i] = g_sel[i];
        if (tid == 0) s_n = n;
    } else {
        // exact slow path: radix refinement over per-class arrays (massive-tie case)
        unsigned long long prefix = B1;
        unsigned int need = KTOP - above;
        int s = 42;
        for (int lvl = 0; lvl < 3; lvl++) {
            s -= 13;
            for (int i = tid; i < NBKT; i += 1024) shist[i] = 0;
            __syncthreads();
            for (int cc = 0; cc < NC; cc++) {
                unsigned int n = min(g_count[cc], (unsigned int)MAXCAND);
                for (unsigned int i = tid; i < n; i += 1024) {
                    unsigned long long k = gkey(g_cand[cc][i], cc);
                    if ((k >> (s + 13)) == prefix)
                        atomicAdd(&shist[(unsigned int)(k >> s) & 8191u], 1u);
                }
            }
            __syncthreads();
            find_boundary(shist, psums, wsums, need, bout);
            prefix = (prefix << 13) | bout[0];
            need -= bout[1];
            if (bout[2] <= CAP - KTOP || s == 3) break;
            __syncthreads();
        }
        if (tid == 0) s_n = 0;
        __syncthreads();
        for (int cc = 0; cc < NC; cc++) {
            unsigned int n = min(g_count[cc], (unsigned int)MAXCAND);
            for (unsigned int i = tid; i < n; i += 1024) {
                unsigned long long k = gkey(g_cand[cc][i], cc);
                if ((k >> s) >= prefix) {
                    unsigned int pos = atomicAdd(&s_n, 1u);
                    if (pos < CAP) sel[pos] = k;
                }
            }
        }
    }
    __syncthreads();

    // ---- rank-select (keys unique => exact): rank = #{keys > mine} ----
    unsigned int n = min(s_n, (unsigned int)CAP);
    if (tid < (int)n) {
        unsigned long long my = sel[tid];
        unsigned int rank = 0;
        for (unsigned int j = 0; j < n; j++)
            rank += (sel[j] > my);
        if (rank < KTOP) {
            unsigned int fk = (unsigned int)(my >> 23);
            int cls = 79 - (int)((my >> 16) & 127ull);
            int spatial = 65535 - (int)(my & 0xFFFFull);
            float logit = fkeyinv(fk);
            float score = 1.0f / (1.0f + expf(-logit));

            int y = spatial >> 8, x = spatial & 255;
            float tx = txty[spatial];
            float ty = txty[HWSZ + spatial];
            float tw = twth[spatial];
            float th = twth[HWSZ + spatial];

            float cx = ((float)x + 1.0f / (1.0f + expf(-tx))) * 4.0f;
            float cy = ((float)y + 1.0f / (1.0f + expf(-ty))) * 4.0f;
            float w2 = expf(tw) * 2.0f;
            float h2 = expf(th) * 2.0f;
            const float inv = 1.0f / 1024.0f;

            out[rank * 4 + 0] = fminf(fmaxf((cx - w2) * inv, 0.0f), 1.0f);
            out[rank * 4 + 1] = fminf(fmaxf((cy - h2) * inv, 0.0f), 1.0f);
            out[rank * 4 + 2] = fminf(fmaxf((cx + w2) * inv, 0.0f), 1.0f);
            out[rank * 4 + 3] = fminf(fmaxf((cy + h2) * inv, 0.0f), 1.0f);
            out[4 * KTOP + rank] = score;
            out[5 * KTOP + rank] = (float)cls;
        }
    }

    // ---- reset scratch for next launch (determinism across graph replays) ----
    __syncthreads();
    for (int i = tid; i < NBKT; i += 1024) g_hist[i] = 0;
    if (tid < NC) g_count[tid] = 0;
    if (tid == 0) { g_selcnt = 0; g_done1 = 0; g_done2 = 0; g_phase = 0; }
}

extern "C" void kernel_launch(void* const* d_in, const int* in_sizes, int n_in,
                              void* d_out, int out_size) {
    const float* cls  = (const float*)d_in[0];
    const float* txty = (const float*)d_in[1];
    const float* twth = (const float*)d_in[2];
    float* out = (float*)d_out;

    dim3 grid(HH / BAND, NC);
    suppress_kernel<<<grid, 256>>>(cls);
    select_kernel<<<NC, 1024>>>(txty, twth, out);
}

// round 16
// speedup vs baseline: 1.7477x; 1.7465x over previous
#include <cuda_runtime.h>
#include <cstdint>

#define HH 256
#define WW 256
#define NC 80
#define HWSZ 65536
#define KTOP 100
#define MAXCAND 8192
#define NBKT 8192
#define CAP  1024
#define BAND 32

// scratch (no cudaMalloc allowed)
__device__ unsigned int        g_count[NC];          // zero-init at load; reset by class_topk
__device__ unsigned long long  g_cand[NC][MAXCAND];
__device__ unsigned int        g_topk_key[NC * KTOP];   // fkey(logit), sorted desc per class
__device__ int                 g_topk_idx[NC * KTOP];   // spatial index in [0,65536)

// monotone float->uint key (handles negatives)
__device__ __forceinline__ unsigned int fkey(float f) {
    unsigned int b = __float_as_uint(f);
    return b ^ ((b & 0x80000000u) ? 0xFFFFFFFFu : 0x80000000u);
}
__device__ __forceinline__ float fkeyinv(unsigned int k) {
    unsigned int b = k ^ ((k & 0x80000000u) ? 0x80000000u : 0xFFFFFFFFu);
    return __uint_as_float(b);
}
__device__ __forceinline__ float4 f4max(float4 a, float4 b) {
    return make_float4(fmaxf(a.x, b.x), fmaxf(a.y, b.y),
                       fmaxf(a.z, b.z), fmaxf(a.w, b.w));
}

// 5x5 strict-window max on logits of batch 0 (exact R10 version).
__global__ __launch_bounds__(256, 4) void suppress_kernel(const float* __restrict__ cls) {
    __shared__ float smvm[BAND][WW + 8];
    const int c   = blockIdx.y;
    const int y0  = blockIdx.x * BAND;
    const int tid = threadIdx.x;
    const int tx  = tid & 63;
    const int ty  = tid >> 6;
    const int lane = tid & 31;
    const float NEG = __int_as_float(0xff800000);
    const float4 NEG4 = make_float4(NEG, NEG, NEG, NEG);
    const float* __restrict__ p = cls + ((size_t)c << 16);
    const float4* __restrict__ p4 = reinterpret_cast<const float4*>(p);

    {
        float4 v[12];
        const int ybase = y0 + ty * 8 - 2;
        #pragma unroll
        for (int r = 0; r < 12; r++) {
            int gy = ybase + r;
            v[r] = (gy >= 0 && gy < HH) ? p4[(gy << 6) | tx] : NEG4;
        }
        {
            int r = tid >> 3, s = tid & 7;
            smvm[r][(s < 4) ? s : (WW + s)] = NEG;
        }
        #pragma unroll
        for (int r = 0; r < 8; r++) {
            float4 vm = f4max(f4max(f4max(v[r], v[r + 1]),
                                    f4max(v[r + 2], v[r + 3])), v[r + 4]);
            *reinterpret_cast<float4*>(&smvm[ty * 8 + r][4 + tx * 4]) = vm;
        }
    }
    __syncthreads();

    unsigned int bm = 0;
    #pragma unroll 2
    for (int r = 0; r < 8; r++) {
        const float* row = smvm[ty * 8 + r];
        float4 L = *reinterpret_cast<const float4*>(&row[tx * 4]);
        float4 C = *reinterpret_cast<const float4*>(&row[tx * 4 + 4]);
        float4 R = *reinterpret_cast<const float4*>(&row[tx * 4 + 8]);
        int rowg = y0 + ty * 8 + r;
        float4 cen = p4[(rowg << 6) | tx];          // L1 hit

        float m12 = fmaxf(C.y, C.z);
        float aa  = fmaxf(C.x, m12);
        float bb  = fmaxf(m12, C.w);
        float ab  = fmaxf(aa, C.w);
        float h0  = fmaxf(fmaxf(L.z, L.w), aa);
        float h1  = fmaxf(L.w, ab);
        float h2  = fmaxf(ab, R.x);
        float h3  = fmaxf(bb, fmaxf(R.x, R.y));

        bm |= (unsigned int)(cen.x == h0) << (r * 4 + 0);
        bm |= (unsigned int)(cen.y == h1) << (r * 4 + 1);
        bm |= (unsigned int)(cen.z == h2) << (r * 4 + 2);
        bm |= (unsigned int)(cen.w == h3) << (r * 4 + 3);
    }

    unsigned int nloc = (unsigned int)__popc(bm);
    unsigned int inc = nloc;
    #pragma unroll
    for (int o = 1; o < 32; o <<= 1) {
        unsigned int t = __shfl_up_sync(0xFFFFFFFFu, inc, o);
        if (lane >= o) inc += t;
    }
    unsigned int total = __shfl_sync(0xFFFFFFFFu, inc, 31);
    if (total) {
        unsigned int base = 0;
        if (lane == 31) base = atomicAdd(&g_count[c], total);
        base = __shfl_sync(0xFFFFFFFFu, base, 31);
        unsigned int pos = base + inc - nloc;
        while (bm) {
            int b = __ffs(bm) - 1;
            bm &= bm - 1;
            int r = b >> 2, s = b & 3;
            int idx = ((y0 + ty * 8 + r) << 8) | (tx * 4 + s);
            float val = p[idx];                     // L1 hit
            if (pos < MAXCAND)
                g_cand[c][pos] = ((unsigned long long)fkey(val) << 32)
                               | (unsigned int)(65535 - idx);
            pos++;
        }
    }
}

// Find smallest bucket B with suffix_count(>=B) >= need over hist[NBKT].
// Block-collective, 1024 threads; warp-parallel. out3: {B, above, suffix(B)}.
__device__ void find_boundary(const unsigned int* hist, unsigned int* psums,
                              unsigned int* wsums, unsigned int need,
                              unsigned int* out3) {
    const int tid = threadIdx.x;
    unsigned int pv0 = 0;
    const int base = tid * 8;
    #pragma unroll
    for (int k = 0; k < 8; k++) pv0 += hist[base + k];
    unsigned int w = pv0;
    #pragma unroll
    for (int o = 16; o; o >>= 1) w += __shfl_down_sync(0xFFFFFFFFu, w, o);
    psums[tid] = pv0;
    if ((tid & 31) == 0) wsums[tid >> 5] = w;
    __syncthreads();
    if (tid < 32) {
        unsigned int wv = wsums[tid];
        unsigned int suf = wv;
        #pragma unroll
        for (int o = 1; o < 32; o <<= 1) {
            unsigned int t = __shfl_down_sync(0xFFFFFFFFu, suf, o);
            if (tid + o < 32) suf += t;
        }
        unsigned int m = __ballot_sync(0xFFFFFFFFu, suf >= need);
        int wstar = m ? (31 - __clz(m)) : 0;
        unsigned int acc = __shfl_sync(0xFFFFFFFFu, suf - wv, wstar);
        unsigned int pv = psums[wstar * 32 + tid];
        unsigned int sufp = pv;
        #pragma unroll
        for (int o = 1; o < 32; o <<= 1) {
            unsigned int t = __shfl_down_sync(0xFFFFFFFFu, sufp, o);
            if (tid + o < 32) sufp += t;
        }
        m = __ballot_sync(0xFFFFFFFFu, acc + sufp >= need);
        int tstar = m ? (31 - __clz(m)) : 0;
        acc = __shfl_sync(0xFFFFFFFFu, acc + sufp - pv, tstar);
        int tglob = wstar * 32 + tstar;
        unsigned int hv = (tid < 8) ? hist[tglob * 8 + tid] : 0;
        unsigned int sufh = hv;
        #pragma unroll
        for (int o = 1; o < 8; o <<= 1) {
            unsigned int t = __shfl_down_sync(0xFFFFFFFFu, sufh, o);
            if (tid + o < 32) sufh += t;
        }
        m = __ballot_sync(0xFFFFFFFFu, (tid < 8) && (acc + sufh >= need)) & 0xFFu;
        int bstar = m ? (31 - __clz(m)) : 0;
        acc = __shfl_sync(0xFFFFFFFFu, acc + sufh - hv, bstar);
        if (tid == 0) {
            unsigned int B = (unsigned int)(tglob * 8 + bstar);
            out3[0] = B;
            out3[1] = acc;
            out3[2] = acc + hist[B];
        }
    }
    __syncthreads();
}

// per-class top-100: histogram select + rank-select scatter (no sort)
__global__ void class_topk_kernel() {
    __shared__ unsigned int hist[NBKT];          // 32 KB
    __shared__ unsigned int psums[1024];         // 4 KB
    __shared__ unsigned int wsums[32];
    __shared__ unsigned int bout[3];
    __shared__ unsigned long long sel[CAP];      // 8 KB
    __shared__ int s_nsel;

    const int c   = blockIdx.x;
    const int tid = threadIdx.x;
    int cnt = (int)min(g_count[c], (unsigned int)MAXCAND);
    if (tid == 0) s_nsel = 0;
    __syncthreads();

    if (cnt > CAP) {
        for (int i = tid; i < NBKT; i += 1024) hist[i] = 0;
        __syncthreads();
        for (int i = tid; i < cnt; i += 1024) {
            unsigned int fk = (unsigned int)(g_cand[c][i] >> 32);
            atomicAdd(&hist[fk >> 19], 1u);
        }
        __syncthreads();
        find_boundary(hist, psums, wsums, KTOP, bout);
        unsigned int B1 = bout[0], above = bout[1], sfx = bout[2];
        unsigned int B2 = 0;
        bool two = false;
        if (sfx > CAP) {                          // refine within boundary bucket
            two = true;
            __syncthreads();
            for (int i = tid; i < NBKT; i += 1024) hist[i] = 0;
            __syncthreads();
            for (int i = tid; i < cnt; i += 1024) {
                unsigned int fk = (unsigned int)(g_cand[c][i] >> 32);
                if ((fk >> 19) == B1) atomicAdd(&hist[(fk >> 6) & 8191u], 1u);
            }
            __syncthreads();
            find_boundary(hist, psums, wsums, KTOP - above, bout);
            B2 = bout[0];
        }
        for (int i = tid; i < cnt; i += 1024) {
            unsigned long long key = g_cand[c][i];
            unsigned int fk = (unsigned int)(key >> 32);
            unsigned int b = fk >> 19;
            bool take = (b > B1) || (b == B1 && (!two || ((fk >> 6) & 8191u) >= B2));
            if (take) {
                int pos = atomicAdd(&s_nsel, 1);
                if (pos < CAP) sel[pos] = key;
            }
        }
    } else {
        for (int i = tid; i < cnt; i += 1024) sel[i] = g_cand[c][i];
        if (tid == 0) s_nsel = cnt;
    }
    __syncthreads();

    // rank-select scatter: keys unique -> ranks unique & exact
    int nsel = min(s_nsel, CAP);
    if (tid < nsel) {
        unsigned long long my = sel[tid];
        unsigned int rank = 0;
        for (int j = 0; j < nsel; j++)
            rank += (sel[j] > my);
        if (rank < KTOP) {
            g_topk_key[c * KTOP + rank] = (unsigned int)(my >> 32);
            g_topk_idx[c * KTOP + rank] = 65535 - (int)(my & 0xFFFFull);
        }
    }
    // determinism guard for degenerate cnt < KTOP
    if (tid >= nsel && tid < KTOP) {
        g_topk_key[c * KTOP + tid] = 0u;
        g_topk_idx[c * KTOP + tid] = 65535;
    }
    if (tid == 0) g_count[c] = 0;   // reset for next launch (determinism)
}

// global top-100 over 80*100 keys: histogram select + rank-select decode (no sort)
__global__ void global_topk_kernel(const float* __restrict__ txty,
                                   const float* __restrict__ twth,
                                   float* __restrict__ out) {
    __shared__ unsigned int hist[NBKT];
    __shared__ unsigned int psums[1024];
    __shared__ unsigned int wsums[32];
    __shared__ unsigned int bout[3];
    __shared__ unsigned long long sel[CAP];
    __shared__ int s_nsel;

    const int tid = threadIdx.x;
    const int N = NC * KTOP;   // 8000
    if (tid == 0) s_nsel = 0;

    for (int i = tid; i < NBKT; i += 1024) hist[i] = 0;
    __syncthreads();
    for (int i = tid; i < N; i += 1024)
        atomicAdd(&hist[g_topk_key[i] >> 19], 1u);
    __syncthreads();
    find_boundary(hist, psums, wsums, KTOP, bout);
    unsigned int B1 = bout[0], above = bout[1], sfx = bout[2];
    unsigned int B2 = 0;
    bool two = false;
    if (sfx > CAP) {
        two = true;
        __syncthreads();
        for (int i = tid; i < NBKT; i += 1024) hist[i] = 0;
        __syncthreads();
        for (int i = tid; i < N; i += 1024) {
            unsigned int fk = g_topk_key[i];
            if ((fk >> 19) == B1) atomicAdd(&hist[(fk >> 6) & 8191u], 1u);
        }
        __syncthreads();
        find_boundary(hist, psums, wsums, KTOP - above, bout);
        B2 = bout[0];
    }
    for (int i = tid; i < N; i += 1024) {
        unsigned int fk = g_topk_key[i];
        unsigned int b = fk >> 19;
        bool take = (b > B1) || (b == B1 && (!two || ((fk >> 6) & 8191u) >= B2));
        if (take) {
            int pos = atomicAdd(&s_nsel, 1);
            if (pos < CAP)
                sel[pos] = ((unsigned long long)fk << 13) | (unsigned int)(8191 - i);
        }
    }
    __syncthreads();

    // rank-select + direct decode: keys unique -> ranks unique & exact
    int nsel = min(s_nsel, CAP);
    if (tid < nsel) {
        unsigned long long my = sel[tid];
        unsigned int rank = 0;
        for (int j = 0; j < nsel; j++)
            rank += (sel[j] > my);
        if (rank < KTOP) {
            unsigned int fk = (unsigned int)(my >> 13);
            int flat = 8191 - (int)(my & 8191ull);
            int cls = flat / KTOP;
            int spatial = g_topk_idx[flat];
            float logit = fkeyinv(fk);
            float score = 1.0f / (1.0f + expf(-logit));

            int y = spatial >> 8, x = spatial & 255;
            float tx = txty[spatial];
            float ty = txty[HWSZ + spatial];
            float tw = twth[spatial];
            float th = twth[HWSZ + spatial];

            float cx = ((float)x + 1.0f / (1.0f + expf(-tx))) * 4.0f;
            float cy = ((float)y + 1.0f / (1.0f + expf(-ty))) * 4.0f;
            float w2 = expf(tw) * 2.0f;
            float h2 = expf(th) * 2.0f;
            const float inv = 1.0f / 1024.0f;

            out[rank * 4 + 0] = fminf(fmaxf((cx - w2) * inv, 0.0f), 1.0f);
            out[rank * 4 + 1] = fminf(fmaxf((cy - h2) * inv, 0.0f), 1.0f);
            out[rank * 4 + 2] = fminf(fmaxf((cx + w2) * inv, 0.0f), 1.0f);
            out[rank * 4 + 3] = fminf(fmaxf((cy + h2) * inv, 0.0f), 1.0f);
            out[4 * KTOP + rank] = score;
            out[5 * KTOP + rank] = (float)cls;
        }
    }
}

extern "C" void kernel_launch(void* const* d_in, const int* in_sizes, int n_in,
                              void* d_out, int out_size) {
    const float* cls  = (const float*)d_in[0];
    const float* txty = (const float*)d_in[1];
    const float* twth = (const float*)d_in[2];
    float* out = (float*)d_out;

    dim3 grid(HH / BAND, NC);
    suppress_kernel<<<grid, 256>>>(cls);
    class_topk_kernel<<<NC, 1024>>>();
    global_topk_kernel<<<1, 1024>>>(txty, twth, out);
}

// round 17
// speedup vs baseline: 1.7683x; 1.0118x over previous
#include <cuda_runtime.h>
#include <cstdint>

#define HH 256
#define WW 256
#define NC 80
#define HWSZ 65536
#define KTOP 100
#define MAXCAND 8192
#define NBKT 8192
#define CAP  1024
#define BAND 32

// scratch (no cudaMalloc allowed); zero-init at load, reset in-pipeline
__device__ unsigned int        g_count[NC];
__device__ unsigned long long  g_cand[NC][MAXCAND];
__device__ unsigned int        g_topk_key[NC * KTOP];   // fkey, desc-ranked per class
__device__ int                 g_topk_idx[NC * KTOP];   // spatial index
__device__ unsigned int        g_done;

// monotone float->uint key (handles negatives)
__device__ __forceinline__ unsigned int fkey(float f) {
    unsigned int b = __float_as_uint(f);
    return b ^ ((b & 0x80000000u) ? 0xFFFFFFFFu : 0x80000000u);
}
__device__ __forceinline__ float fkeyinv(unsigned int k) {
    unsigned int b = k ^ ((k & 0x80000000u) ? 0x80000000u : 0xFFFFFFFFu);
    return __uint_as_float(b);
}
__device__ __forceinline__ float4 f4max(float4 a, float4 b) {
    return make_float4(fmaxf(a.x, b.x), fmaxf(a.y, b.y),
                       fmaxf(a.z, b.z), fmaxf(a.w, b.w));
}

// 5x5 strict-window max on logits of batch 0 (exact R10/R16 version).
__global__ __launch_bounds__(256, 4) void suppress_kernel(const float* __restrict__ cls) {
    __shared__ float smvm[BAND][WW + 8];
    const int c   = blockIdx.y;
    const int y0  = blockIdx.x * BAND;
    const int tid = threadIdx.x;
    const int tx  = tid & 63;
    const int ty  = tid >> 6;
    const int lane = tid & 31;
    const float NEG = __int_as_float(0xff800000);
    const float4 NEG4 = make_float4(NEG, NEG, NEG, NEG);
    const float* __restrict__ p = cls + ((size_t)c << 16);
    const float4* __restrict__ p4 = reinterpret_cast<const float4*>(p);

    {
        float4 v[12];
        const int ybase = y0 + ty * 8 - 2;
        #pragma unroll
        for (int r = 0; r < 12; r++) {
            int gy = ybase + r;
            v[r] = (gy >= 0 && gy < HH) ? p4[(gy << 6) | tx] : NEG4;
        }
        {
            int r = tid >> 3, s = tid & 7;
            smvm[r][(s < 4) ? s : (WW + s)] = NEG;
        }
        #pragma unroll
        for (int r = 0; r < 8; r++) {
            float4 vm = f4max(f4max(f4max(v[r], v[r + 1]),
                                    f4max(v[r + 2], v[r + 3])), v[r + 4]);
            *reinterpret_cast<float4*>(&smvm[ty * 8 + r][4 + tx * 4]) = vm;
        }
    }
    __syncthreads();

    unsigned int bm = 0;
    #pragma unroll 2
    for (int r = 0; r < 8; r++) {
        const float* row = smvm[ty * 8 + r];
        float4 L = *reinterpret_cast<const float4*>(&row[tx * 4]);
        float4 C = *reinterpret_cast<const float4*>(&row[tx * 4 + 4]);
        float4 R = *reinterpret_cast<const float4*>(&row[tx * 4 + 8]);
        int rowg = y0 + ty * 8 + r;
        float4 cen = p4[(rowg << 6) | tx];          // L1 hit

        float m12 = fmaxf(C.y, C.z);
        float aa  = fmaxf(C.x, m12);
        float bb  = fmaxf(m12, C.w);
        float ab  = fmaxf(aa, C.w);
        float h0  = fmaxf(fmaxf(L.z, L.w), aa);
        float h1  = fmaxf(L.w, ab);
        float h2  = fmaxf(ab, R.x);
        float h3  = fmaxf(bb, fmaxf(R.x, R.y));

        bm |= (unsigned int)(cen.x == h0) << (r * 4 + 0);
        bm |= (unsigned int)(cen.y == h1) << (r * 4 + 1);
        bm |= (unsigned int)(cen.z == h2) << (r * 4 + 2);
        bm |= (unsigned int)(cen.w == h3) << (r * 4 + 3);
    }

    unsigned int nloc = (unsigned int)__popc(bm);
    unsigned int inc = nloc;
    #pragma unroll
    for (int o = 1; o < 32; o <<= 1) {
        unsigned int t = __shfl_up_sync(0xFFFFFFFFu, inc, o);
        if (lane >= o) inc += t;
    }
    unsigned int total = __shfl_sync(0xFFFFFFFFu, inc, 31);
    if (total) {
        unsigned int base = 0;
        if (lane == 31) base = atomicAdd(&g_count[c], total);
        base = __shfl_sync(0xFFFFFFFFu, base, 31);
        unsigned int pos = base + inc - nloc;
        while (bm) {
            int b = __ffs(bm) - 1;
            bm &= bm - 1;
            int r = b >> 2, s = b & 3;
            int idx = ((y0 + ty * 8 + r) << 8) | (tx * 4 + s);
            float val = p[idx];                     // L1 hit
            if (pos < MAXCAND)
                g_cand[c][pos] = ((unsigned long long)fkey(val) << 32)
                               | (unsigned int)(65535 - idx);
            pos++;
        }
    }
}

// Find smallest bucket B with suffix_count(>=B) >= need over hist[NBKT].
// Block-collective, 1024 threads; warp-parallel. out3: {B, above, suffix(B)}.
__device__ void find_boundary(const unsigned int* hist, unsigned int* psums,
                              unsigned int* wsums, unsigned int need,
                              unsigned int* out3) {
    const int tid = threadIdx.x;
    unsigned int pv0 = 0;
    const int base = tid * 8;
    #pragma unroll
    for (int k = 0; k < 8; k++) pv0 += hist[base + k];
    unsigned int w = pv0;
    #pragma unroll
    for (int o = 16; o; o >>= 1) w += __shfl_down_sync(0xFFFFFFFFu, w, o);
    psums[tid] = pv0;
    if ((tid & 31) == 0) wsums[tid >> 5] = w;
    __syncthreads();
    if (tid < 32) {
        unsigned int wv = wsums[tid];
        unsigned int suf = wv;
        #pragma unroll
        for (int o = 1; o < 32; o <<= 1) {
            unsigned int t = __shfl_down_sync(0xFFFFFFFFu, suf, o);
            if (tid + o < 32) suf += t;
        }
        unsigned int m = __ballot_sync(0xFFFFFFFFu, suf >= need);
        int wstar = m ? (31 - __clz(m)) : 0;
        unsigned int acc = __shfl_sync(0xFFFFFFFFu, suf - wv, wstar);
        unsigned int pv = psums[wstar * 32 + tid];
        unsigned int sufp = pv;
        #pragma unroll
        for (int o = 1; o < 32; o <<= 1) {
            unsigned int t = __shfl_down_sync(0xFFFFFFFFu, sufp, o);
            if (tid + o < 32) sufp += t;
        }
        m = __ballot_sync(0xFFFFFFFFu, acc + sufp >= need);
        int tstar = m ? (31 - __clz(m)) : 0;
        acc = __shfl_sync(0xFFFFFFFFu, acc + sufp - pv, tstar);
        int tglob = wstar * 32 + tstar;
        unsigned int hv = (tid < 8) ? hist[tglob * 8 + tid] : 0;
        unsigned int sufh = hv;
        #pragma unroll
        for (int o = 1; o < 8; o <<= 1) {
            unsigned int t = __shfl_down_sync(0xFFFFFFFFu, sufh, o);
            if (tid + o < 32) sufh += t;
        }
        m = __ballot_sync(0xFFFFFFFFu, (tid < 8) && (acc + sufh >= need)) & 0xFFu;
        int bstar = m ? (31 - __clz(m)) : 0;
        acc = __shfl_sync(0xFFFFFFFFu, acc + sufh - hv, bstar);
        if (tid == 0) {
            unsigned int B = (unsigned int)(tglob * 8 + bstar);
            out3[0] = B;
            out3[1] = acc;
            out3[2] = acc + hist[B];
        }
    }
    __syncthreads();
}

// Fused: per-class top-100 (R16 class phase) -> ticket -> last block runs the
// R16 global phase (smem hist + rank-select decode) and resets scratch.
__global__ __launch_bounds__(1024) void select_kernel(
        const float* __restrict__ txty,
        const float* __restrict__ twth,
        float* __restrict__ out) {
    __shared__ unsigned int hist[NBKT];          // 32 KB
    __shared__ unsigned int psums[1024];         // 4 KB
    __shared__ unsigned int wsums[32];
    __shared__ unsigned int bout[3];
    __shared__ unsigned long long sel[CAP];      // 8 KB
    __shared__ int s_nsel;
    __shared__ unsigned int s_last;

    const int c   = blockIdx.x;
    const int tid = threadIdx.x;

    // ================= class phase (identical to R16 class_topk) =============
    int cnt = (int)min(g_count[c], (unsigned int)MAXCAND);
    if (tid == 0) s_nsel = 0;
    __syncthreads();

    if (cnt > CAP) {
        for (int i = tid; i < NBKT; i += 1024) hist[i] = 0;
        __syncthreads();
        for (int i = tid; i < cnt; i += 1024) {
            unsigned int fk = (unsigned int)(g_cand[c][i] >> 32);
            atomicAdd(&hist[fk >> 19], 1u);
        }
        __syncthreads();
        find_boundary(hist, psums, wsums, KTOP, bout);
        unsigned int B1 = bout[0], above = bout[1], sfx = bout[2];
        unsigned int B2 = 0;
        bool two = false;
        if (sfx > CAP) {                          // refine within boundary bucket
            two = true;
            __syncthreads();
            for (int i = tid; i < NBKT; i += 1024) hist[i] = 0;
            __syncthreads();
            for (int i = tid; i < cnt; i += 1024) {
                unsigned int fk = (unsigned int)(g_cand[c][i] >> 32);
                if ((fk >> 19) == B1) atomicAdd(&hist[(fk >> 6) & 8191u], 1u);
            }
            __syncthreads();
            find_boundary(hist, psums, wsums, KTOP - above, bout);
            B2 = bout[0];
        }
        for (int i = tid; i < cnt; i += 1024) {
            unsigned long long key = g_cand[c][i];
            unsigned int fk = (unsigned int)(key >> 32);
            unsigned int b = fk >> 19;
            bool take = (b > B1) || (b == B1 && (!two || ((fk >> 6) & 8191u) >= B2));
            if (take) {
                int pos = atomicAdd(&s_nsel, 1);
                if (pos < CAP) sel[pos] = key;
            }
        }
    } else {
        for (int i = tid; i < cnt; i += 1024) sel[i] = g_cand[c][i];
        if (tid == 0) s_nsel = cnt;
    }
    __syncthreads();

    // rank-select scatter: keys unique -> ranks unique & exact
    int nsel = min(s_nsel, CAP);
    if (tid < nsel) {
        unsigned long long my = sel[tid];
        unsigned int rank = 0;
        for (int j = 0; j < nsel; j++)
            rank += (sel[j] > my);
        if (rank < KTOP) {
            g_topk_key[c * KTOP + rank] = (unsigned int)(my >> 32);
            g_topk_idx[c * KTOP + rank] = 65535 - (int)(my & 0xFFFFull);
        }
    }
    if (tid >= nsel && tid < KTOP) {              // degenerate cnt < KTOP guard
        g_topk_key[c * KTOP + tid] = 0u;
        g_topk_idx[c * KTOP + tid] = 65535;
    }
    if (tid == 0) g_count[c] = 0;                 // reset for next launch

    // ================= ticket: last block runs global phase ==================
    __syncthreads();
    __threadfence();
    if (tid == 0) s_last = atomicAdd(&g_done, 1u);
    __syncthreads();
    if (s_last != NC - 1) return;

    // ================= global phase (identical to R16 global_topk) ===========
    const int N = NC * KTOP;   // 8000
    if (tid == 0) s_nsel = 0;

    for (int i = tid; i < NBKT; i += 1024) hist[i] = 0;
    __syncthreads();
    for (int i = tid; i < N; i += 1024)
        atomicAdd(&hist[g_topk_key[i] >> 19], 1u);
    __syncthreads();
    find_boundary(hist, psums, wsums, KTOP, bout);
    unsigned int B1 = bout[0], above = bout[1], sfx = bout[2];
    unsigned int B2 = 0;
    bool two = false;
    if (sfx > CAP) {
        two = true;
        __syncthreads();
        for (int i = tid; i < NBKT; i += 1024) hist[i] = 0;
        __syncthreads();
        for (int i = tid; i < N; i += 1024) {
            unsigned int fk = g_topk_key[i];
            if ((fk >> 19) == B1) atomicAdd(&hist[(fk >> 6) & 8191u], 1u);
        }
        __syncthreads();
        find_boundary(hist, psums, wsums, KTOP - above, bout);
        B2 = bout[0];
    }
    for (int i = tid; i < N; i += 1024) {
        unsigned int fk = g_topk_key[i];
        unsigned int b = fk >> 19;
        bool take = (b > B1) || (b == B1 && (!two || ((fk >> 6) & 8191u) >= B2));
        if (take) {
            int pos = atomicAdd(&s_nsel, 1);
            if (pos < CAP)
                sel[pos] = ((unsigned long long)fk << 13) | (unsigned int)(8191 - i);
        }
    }
    __syncthreads();

    nsel = min(s_nsel, CAP);
    if (tid < nsel) {
        unsigned long long my = sel[tid];
        unsigned int rank = 0;
        for (int j = 0; j < nsel; j++)
            rank += (sel[j] > my);
        if (rank < KTOP) {
            unsigned int fk = (unsigned int)(my >> 13);
            int flat = 8191 - (int)(my & 8191ull);
            int cls = flat / KTOP;
            int spatial = g_topk_idx[flat];
            float logit = fkeyinv(fk);
            float score = 1.0f / (1.0f + expf(-logit));

            int y = spatial >> 8, x = spatial & 255;
            float tx = txty[spatial];
            float ty = txty[HWSZ + spatial];
            float tw = twth[spatial];
            float th = twth[HWSZ + spatial];

            float cx = ((float)x + 1.0f / (1.0f + expf(-tx))) * 4.0f;
            float cy = ((float)y + 1.0f / (1.0f + expf(-ty))) * 4.0f;
            float w2 = expf(tw) * 2.0f;
            float h2 = expf(th) * 2.0f;
            const float inv = 1.0f / 1024.0f;

            out[rank * 4 + 0] = fminf(fmaxf((cx - w2) * inv, 0.0f), 1.0f);
            out[rank * 4 + 1] = fminf(fmaxf((cy - h2) * inv, 0.0f), 1.0f);
            out[rank * 4 + 2] = fminf(fmaxf((cx + w2) * inv, 0.0f), 1.0f);
            out[rank * 4 + 3] = fminf(fmaxf((cy + h2) * inv, 0.0f), 1.0f);
            out[4 * KTOP + rank] = score;
            out[5 * KTOP + rank] = (float)cls;
        }
    }

    __syncthreads();
    if (tid == 0) g_done = 0;                     // reset ticket for next launch
}

extern "C" void kernel_launch(void* const* d_in, const int* in_sizes, int n_in,
                              void* d_out, int out_size) {
    const float* cls  = (const float*)d_in[0];
    const float* txty = (const float*)d_in[1];
    const float* twth = (const float*)d_in[2];
    float* out = (float*)d_out;

    dim3 grid(HH / BAND, NC);
    suppress_kernel<<<grid, 256>>>(cls);
    select_kernel<<<NC, 1024>>>(txty, twth, out);
}